// round 13
// baseline (speedup 1.0000x reference)
#include <cuda_runtime.h>
#include <cuda_fp16.h>
#include <math.h>

#define NMAX 100000
#define EMAX 3200000
#define GNUM 64
#define FIN  128
#define SCB  1024
#define NBLK ((NMAX + SCB - 1) / SCB)

// -------- device scratch --------
__device__ uint4  g_A[(size_t)NMAX * 8];     // N x (<=64) halfs, ping
__device__ uint4  g_B[(size_t)NMAX * 8];     // pong
__device__ float  g_dinv[NMAX];
__device__ int    g_deg [NMAX];
__device__ int    g_rowptr[NMAX + 1];        // block-local exclusive; [n]=total
__device__ int    g_bsum[NBLK];
__device__ int    g_boff[NBLK];
__device__ int    g_done;
__device__ int    g_rank[EMAX];
__device__ int    g_csrc[EMAX];

__device__ __forceinline__ int rp(int i, int n) {
    return (i < n) ? (g_rowptr[i] + g_boff[i / SCB]) : g_rowptr[n];
}

// -------- half helpers --------
__device__ __forceinline__ float2 uph(unsigned v) {
    __half2 h = *reinterpret_cast<__half2*>(&v);
    return __half22float2(h);
}
__device__ __forceinline__ unsigned pack2(float x, float y) {
    __half2 h = __floats2half2_rn(x, y);
    return *reinterpret_cast<unsigned*>(&h);
}
__device__ __forceinline__ uint2 pack4(float4 a) {
    return make_uint2(pack2(a.x, a.y), pack2(a.z, a.w));
}
__device__ __forceinline__ void acc8(float* a, uint4 u) {
    float2 f0 = uph(u.x), f1 = uph(u.y), f2 = uph(u.z), f3 = uph(u.w);
    a[0] += f0.x; a[1] += f0.y; a[2] += f1.x; a[3] += f1.y;
    a[4] += f2.x; a[5] += f2.y; a[6] += f3.x; a[7] += f3.y;
}

// -------- degree count on dst + per-edge rank --------
__global__ void k_prep(const int* __restrict__ ei, int E, int n) {
    int base = 2 * (blockIdx.x * blockDim.x + threadIdx.x);
    if (base >= E) return;
    if (base + 1 < E) {
        int2 d2 = *(const int2*)(ei + E + base);
        int d0 = ((unsigned)d2.x < (unsigned)n) ? d2.x : 0;
        int d1 = ((unsigned)d2.y < (unsigned)n) ? d2.y : 0;
        int r0 = atomicAdd(&g_deg[d0], 1);
        int r1 = atomicAdd(&g_deg[d1], 1);
        *(int2*)(g_rank + base) = make_int2(r0, r1);
    } else {
        int d = ei[E + base];
        if ((unsigned)d >= (unsigned)n) d = 0;
        g_rank[base] = atomicAdd(&g_deg[d], 1);
    }
}

// -------- scan phase 1 (+dinv), fused phase 2 in last block --------
__global__ void k_scan1(int n, int nb) {
    __shared__ int wsum[32];
    __shared__ bool lastblk;
    int t = threadIdx.x, lane = t & 31, w = t >> 5;
    int i = blockIdx.x * SCB + t;
    int v = (i < n) ? g_deg[i] : 0;
    if (i < n) g_dinv[i] = rsqrtf((float)v + 1.0f);
    int inc = v;
    #pragma unroll
    for (int o = 1; o < 32; o <<= 1) {
        int u = __shfl_up_sync(0xffffffffu, inc, o);
        if (lane >= o) inc += u;
    }
    if (lane == 31) wsum[w] = inc;
    __syncthreads();
    if (w == 0) {
        int s = wsum[lane];
        int sinc = s;
        #pragma unroll
        for (int o = 1; o < 32; o <<= 1) {
            int u = __shfl_up_sync(0xffffffffu, sinc, o);
            if (lane >= o) sinc += u;
        }
        wsum[lane] = sinc - s;
        if (lane == 31) g_bsum[blockIdx.x] = sinc;
    }
    __syncthreads();
    if (i < n) g_rowptr[i] = wsum[w] + inc - v;

    __threadfence();
    if (t == 0) lastblk = (atomicAdd(&g_done, 1) == nb - 1);
    __syncthreads();
    if (!lastblk) return;
    int v2 = (t < nb) ? g_bsum[t] : 0;
    int inc2 = v2;
    #pragma unroll
    for (int o = 1; o < 32; o <<= 1) {
        int u = __shfl_up_sync(0xffffffffu, inc2, o);
        if (lane >= o) inc2 += u;
    }
    __syncthreads();
    if (lane == 31) wsum[w] = inc2;
    __syncthreads();
    if (w == 0) {
        int s = wsum[lane];
        int sinc = s;
        #pragma unroll
        for (int o = 1; o < 32; o <<= 1) {
            int u = __shfl_up_sync(0xffffffffu, sinc, o);
            if (lane >= o) sinc += u;
        }
        wsum[lane] = sinc - s;
        if (lane == 31) g_rowptr[n] = sinc;
    }
    __syncthreads();
    if (t < nb) g_boff[t] = wsum[w] + inc2 - v2;
    if (t == 0) g_done = 0;
}

// -------- CSR fill: no atomics --------
__global__ void k_fill(const int* __restrict__ ei, int E, int n) {
    int base = 2 * (blockIdx.x * blockDim.x + threadIdx.x);
    if (base >= E) return;
    if (base + 1 < E) {
        int2 s2 = *(const int2*)(ei + base);
        int2 d2 = *(const int2*)(ei + E + base);
        int2 r2 = *(const int2*)(g_rank + base);
        int s0 = ((unsigned)s2.x < (unsigned)n) ? s2.x : 0;
        int s1 = ((unsigned)s2.y < (unsigned)n) ? s2.y : 0;
        int d0 = ((unsigned)d2.x < (unsigned)n) ? d2.x : 0;
        int d1 = ((unsigned)d2.y < (unsigned)n) ? d2.y : 0;
        g_csrc[rp(d0, n) + r2.x] = s0;
        g_csrc[rp(d1, n) + r2.y] = s1;
    } else {
        int s = ei[base], d = ei[E + base];
        if ((unsigned)s >= (unsigned)n || (unsigned)d >= (unsigned)n) { s = 0; d = 0; }
        g_csrc[rp(d, n) + g_rank[base]] = s;
    }
}

// -------- butterfly reduction step: 2*CNT accs -> CNT accs across lane-bit CNT --
template<int CNT>
__device__ __forceinline__ void red_step(float* a, int lane) {
    bool hi = (lane & CNT) != 0;
    #pragma unroll
    for (int m = 0; m < CNT; m++) {
        float lo_v = a[m], hi_v = a[m + CNT];
        float mine = hi ? hi_v : lo_v;
        float send = hi ? lo_v : hi_v;
        a[m] = mine + __shfl_xor_sync(0xffffffffu, send, CNT);
    }
}
__device__ __forceinline__ void red16(float* a, int lane) {
    #pragma unroll
    for (int m = 0; m < 16; m++) a[m] += __shfl_xor_sync(0xffffffffu, a[m], 16);
    red_step<8>(a, lane);
    red_step<4>(a, lane);
    red_step<2>(a, lane);
    red_step<1>(a, lane);
    // now a[0] at lane L is output index (L & 15)
}

// -------- layer-1 GEMM (128->16), warp per 4 nodes, lanes index K ------------
// Coalesced 512B row loads; Wt[m][k4] staged transposed in smem; butterfly out.
__global__ void k_gemm1t(const float* __restrict__ X, const float* __restrict__ W,
                         __half* __restrict__ OUT, int n) {
    __shared__ float4 Wt[16 * 32];   // [m][k4]
    int tid = threadIdx.x;
    for (int i = tid; i < 512; i += blockDim.x) {
        int m = i >> 5, k4 = i & 31;
        Wt[i] = make_float4(W[(4 * k4 + 0) * 16 + m], W[(4 * k4 + 1) * 16 + m],
                            W[(4 * k4 + 2) * 16 + m], W[(4 * k4 + 3) * 16 + m]);
    }
    __syncthreads();
    int w = tid >> 5, lane = tid & 31;
    int nb = (blockIdx.x * 8 + w) * 4;
    if (nb >= n) return;
    float4 z = make_float4(0.f, 0.f, 0.f, 0.f);
    float4 x0 = (nb + 0 < n) ? ((const float4*)(X + (size_t)(nb + 0) * 128))[lane] : z;
    float4 x1 = (nb + 1 < n) ? ((const float4*)(X + (size_t)(nb + 1) * 128))[lane] : z;
    float4 x2 = (nb + 2 < n) ? ((const float4*)(X + (size_t)(nb + 2) * 128))[lane] : z;
    float4 x3 = (nb + 3 < n) ? ((const float4*)(X + (size_t)(nb + 3) * 128))[lane] : z;
    float a0[16], a1[16], a2[16], a3[16];
    #pragma unroll
    for (int m = 0; m < 16; m++) {
        float4 wv = Wt[m * 32 + lane];
        a0[m] = x0.x * wv.x + x0.y * wv.y + x0.z * wv.z + x0.w * wv.w;
        a1[m] = x1.x * wv.x + x1.y * wv.y + x1.z * wv.z + x1.w * wv.w;
        a2[m] = x2.x * wv.x + x2.y * wv.y + x2.z * wv.z + x2.w * wv.w;
        a3[m] = x3.x * wv.x + x3.y * wv.y + x3.z * wv.z + x3.w * wv.w;
    }
    red16(a0, lane); red16(a1, lane); red16(a2, lane); red16(a3, lane);
    int m = lane & 15;
    if (lane < 16) {
        if (nb + 0 < n) OUT[(size_t)(nb + 0) * 16 + m] = __float2half(a0[0] * g_dinv[nb + 0]);
        if (nb + 1 < n) OUT[(size_t)(nb + 1) * 16 + m] = __float2half(a1[0] * g_dinv[nb + 1]);
    } else {
        if (nb + 2 < n) OUT[(size_t)(nb + 2) * 16 + m] = __float2half(a2[0] * g_dinv[nb + 2]);
        if (nb + 3 < n) OUT[(size_t)(nb + 3) * 16 + m] = __float2half(a3[0] * g_dinv[nb + 3]);
    }
}

// -------- GEMM half in, half out (layer 3: 64->32, *dinv)  [R11 version] -----
template<int K, int MOUT>
__global__ void k_gemmh(const uint4* __restrict__ X, const float* __restrict__ W,
                        uint2* __restrict__ OUT, int n) {
    constexpr int C = K / 8, M4 = MOUT / 4;
    __shared__ float4 Ws[K * M4];
    int tid = threadIdx.x;
    for (int i = tid; i < K * M4; i += blockDim.x)
        Ws[i] = ((const float4*)W)[i];
    __syncthreads();
    int node = blockIdx.x * blockDim.x + tid;
    if (node >= n) return;
    const uint4* xr = X + (size_t)node * C;
    float4 acc[M4];
    #pragma unroll
    for (int m = 0; m < M4; m++) acc[m] = make_float4(0.f, 0.f, 0.f, 0.f);
    #pragma unroll
    for (int c = 0; c < C; c++) {
        uint4 u = __ldg(&xr[c]);
        float xk[8];
        float2 f0 = uph(u.x), f1 = uph(u.y), f2 = uph(u.z), f3 = uph(u.w);
        xk[0] = f0.x; xk[1] = f0.y; xk[2] = f1.x; xk[3] = f1.y;
        xk[4] = f2.x; xk[5] = f2.y; xk[6] = f3.x; xk[7] = f3.y;
        #pragma unroll
        for (int kk = 0; kk < 8; kk++) {
            float xv = xk[kk];
            #pragma unroll
            for (int m = 0; m < M4; m++) {
                float4 w = Ws[(8 * c + kk) * M4 + m];
                acc[m].x += xv * w.x; acc[m].y += xv * w.y;
                acc[m].z += xv * w.z; acc[m].w += xv * w.w;
            }
        }
    }
    float sc = g_dinv[node];
    uint2* orow = OUT + (size_t)node * M4;
    #pragma unroll
    for (int m = 0; m < M4; m++) {
        float4 a = acc[m];
        a.x *= sc; a.y *= sc; a.z *= sc; a.w *= sc;
        orow[m] = pack4(a);
    }
}

// -------- warp-per-node half gather --------
template<int F, bool RELU, bool HASB, bool SCALEOUT>
__global__ void k_gatherh(const uint4* __restrict__ src, uint4* __restrict__ dst,
                          const float* __restrict__ bias, int n) {
    constexpr int LPR = F / 8;
    constexpr int EPW = 32 / LPR;
    int wid = (blockIdx.x * blockDim.x + threadIdx.x) >> 5;
    if (wid >= n) return;
    int lane = threadIdx.x & 31;
    int e_l = lane / LPR;
    int g   = lane % LPR;
    int beg = rp(wid, n), end = rp(wid + 1, n);
    float a0[8] = {0,0,0,0,0,0,0,0};
    float a1[8] = {0,0,0,0,0,0,0,0};
    int j = beg + e_l;
    for (; j + EPW < end; j += 2 * EPW) {
        int s0 = __ldg(&g_csrc[j]);
        int s1 = __ldg(&g_csrc[j + EPW]);
        uint4 u0 = __ldg(&src[(size_t)s0 * LPR + g]);
        uint4 u1 = __ldg(&src[(size_t)s1 * LPR + g]);
        acc8(a0, u0);
        acc8(a1, u1);
    }
    if (j < end) {
        int s0 = __ldg(&g_csrc[j]);
        uint4 u0 = __ldg(&src[(size_t)s0 * LPR + g]);
        acc8(a0, u0);
    }
    #pragma unroll
    for (int q = 0; q < 8; q++) a0[q] += a1[q];
    #pragma unroll
    for (int off = 16; off >= LPR; off >>= 1) {
        #pragma unroll
        for (int q = 0; q < 8; q++)
            a0[q] += __shfl_xor_sync(0xffffffffu, a0[q], off);
    }
    if (lane < LPR) {
        uint4 hv = src[(size_t)wid * LPR + g];
        acc8(a0, hv);
        float di = g_dinv[wid];
        #pragma unroll
        for (int q = 0; q < 8; q++) a0[q] *= di;
        if (HASB) {
            #pragma unroll
            for (int q = 0; q < 8; q++) a0[q] += __ldg(&bias[8 * g + q]);
        }
        if (RELU) {
            #pragma unroll
            for (int q = 0; q < 8; q++) a0[q] = fmaxf(a0[q], 0.f);
        }
        if (SCALEOUT) {
            #pragma unroll
            for (int q = 0; q < 8; q++) a0[q] *= di;
        }
        uint4 o;
        o.x = pack2(a0[0], a0[1]); o.y = pack2(a0[2], a0[3]);
        o.z = pack2(a0[4], a0[5]); o.w = pack2(a0[6], a0[7]);
        dst[(size_t)wid * LPR + g] = o;
    }
}

// -------- FUSED layer 2: gather(16) + GEMM 16->64 + bias + relu --------
__global__ void k_g2g(const uint4* __restrict__ src, const float* __restrict__ W2,
                      const float* __restrict__ b2, __half* __restrict__ OUT, int n) {
    __shared__ float Ws[16 * 64];
    int tid = threadIdx.x;
    for (int i = tid; i < 16 * 64; i += blockDim.x) Ws[i] = W2[i];
    __syncthreads();
    int wid = (blockIdx.x * blockDim.x + tid) >> 5;
    if (wid >= n) return;
    int lane = tid & 31;
    int e_l = lane >> 1;
    int g   = lane & 1;
    int beg = rp(wid, n), end = rp(wid + 1, n);
    float a0[8] = {0,0,0,0,0,0,0,0};
    float a1[8] = {0,0,0,0,0,0,0,0};
    int j = beg + e_l;
    for (; j + 16 < end; j += 32) {
        int s0 = __ldg(&g_csrc[j]);
        int s1 = __ldg(&g_csrc[j + 16]);
        uint4 u0 = __ldg(&src[(size_t)s0 * 2 + g]);
        uint4 u1 = __ldg(&src[(size_t)s1 * 2 + g]);
        acc8(a0, u0);
        acc8(a1, u1);
    }
    if (j < end) {
        int s0 = __ldg(&g_csrc[j]);
        uint4 u0 = __ldg(&src[(size_t)s0 * 2 + g]);
        acc8(a0, u0);
    }
    #pragma unroll
    for (int q = 0; q < 8; q++) a0[q] += a1[q];
    #pragma unroll
    for (int off = 16; off >= 2; off >>= 1) {
        #pragma unroll
        for (int q = 0; q < 8; q++)
            a0[q] += __shfl_xor_sync(0xffffffffu, a0[q], off);
    }
    uint4 hv = __ldg(&src[(size_t)wid * 2 + g]);
    acc8(a0, hv);
    float di = g_dinv[wid];
    #pragma unroll
    for (int q = 0; q < 8; q++) a0[q] *= di;
    float agg[16];
    #pragma unroll
    for (int q = 0; q < 8; q++) {
        agg[q]     = __shfl_sync(0xffffffffu, a0[q], 0);
        agg[8 + q] = __shfl_sync(0xffffffffu, a0[q], 1);
    }
    float acc1 = __ldg(&b2[lane]);
    float acc2 = __ldg(&b2[lane + 32]);
    #pragma unroll
    for (int k = 0; k < 16; k++) {
        acc1 += agg[k] * Ws[k * 64 + lane];
        acc2 += agg[k] * Ws[k * 64 + lane + 32];
    }
    __half* orow = OUT + (size_t)wid * 64;
    orow[lane]      = __float2half(fmaxf(acc1, 0.f));
    orow[lane + 32] = __float2half(fmaxf(acc2, 0.f));
}

// -------- FUSED mean pool + MLP head --------
__global__ void k_poolhead(const __half* __restrict__ fsrc, const int* __restrict__ batch,
                           const float* __restrict__ Wa, const float* __restrict__ ba,
                           const float* __restrict__ Wo, const float* __restrict__ bo,
                           float* __restrict__ out, int n) {
    __shared__ int bounds[2];
    __shared__ float sh[256];
    __shared__ float ps[32];
    __shared__ float a[64];
    int g = blockIdx.x;
    int t = threadIdx.x;
    if (t == 0) {
        int lo = 0, hi = n;
        while (lo < hi) { int mid = (lo + hi) >> 1; if (batch[mid] < g) lo = mid + 1; else hi = mid; }
        bounds[0] = lo;
        int lo2 = lo; hi = n;
        while (lo2 < hi) { int mid = (lo2 + hi) >> 1; if (batch[mid] < g + 1) lo2 = mid + 1; else hi = mid; }
        bounds[1] = lo2;
    }
    __syncthreads();
    int beg = bounds[0], cnt = bounds[1] - bounds[0];
    int f = t & 31, p = t >> 5;
    float s = 0.f;
    for (int k = p; k < cnt; k += 8)
        s += __half2float(fsrc[(size_t)(beg + k) * 32 + f]);
    sh[t] = s;
    __syncthreads();
    if (p == 0) {
        float tot = 0.f;
        #pragma unroll
        for (int q = 0; q < 8; q++) tot += sh[q * 32 + f];
        ps[f] = tot / fmaxf((float)cnt, 1.f);
    }
    __syncthreads();
    if (t < 64) {
        float acc = ba[t];
        #pragma unroll
        for (int k = 0; k < 32; k++) acc += ps[k] * Wa[k * 64 + t];
        a[t] = fmaxf(acc, 0.f);
    }
    __syncthreads();
    if (t < 32) {
        float o = bo[t];
        #pragma unroll
        for (int k = 0; k < 64; k++) o += a[k] * Wo[k * 32 + t];
        out[g * 32 + t] = tanhf(o);
    }
}

// ============================================================================
extern "C" void kernel_launch(void* const* d_in, const int* in_sizes, int n_in,
                              void* d_out, int out_size) {
    const float* x     = (const float*)d_in[0];
    const int*   ei    = (const int*)d_in[1];
    const int*   batch = (const int*)d_in[2];
    const float* W1 = (const float*)d_in[3];  const float* b1 = (const float*)d_in[4];
    const float* W2 = (const float*)d_in[5];  const float* b2 = (const float*)d_in[6];
    const float* W3 = (const float*)d_in[7];  const float* b3 = (const float*)d_in[8];
    const float* Wa = (const float*)d_in[9];  const float* ba = (const float*)d_in[10];
    const float* Wo = (const float*)d_in[11]; const float* bo = (const float*)d_in[12];
    float* out = (float*)d_out;

    int N = in_sizes[0] / FIN;
    int E = in_sizes[1] / 2;
    if (N > NMAX) N = NMAX;
    if (E > EMAX) E = EMAX;
    int nb = (N + SCB - 1) / SCB;

    void *pA = nullptr, *pB = nullptr, *pDeg = nullptr;
    cudaGetSymbolAddress(&pA, g_A);
    cudaGetSymbolAddress(&pB, g_B);
    cudaGetSymbolAddress(&pDeg, g_deg);
    uint4* A4 = (uint4*)pA;
    uint4* B4 = (uint4*)pB;  uint2* B2 = (uint2*)pB;

    const int TB = 256;
    auto blocks = [](long long work, int tb) { return (int)((work + tb - 1) / tb); };
    int gw = blocks((long long)N * 32, TB);
    int gn = blocks(N, TB);
    int g1 = blocks(N, 32);                  // warp per 4 nodes, 8 warps/block

    // ---- CSR build + dinv ----
    cudaMemsetAsync(pDeg, 0, (size_t)N * sizeof(int));
    k_prep<<<blocks((E + 1) / 2, TB), TB>>>(ei, E, N);
    k_scan1<<<nb, SCB>>>(N, nb);
    k_fill<<<blocks((E + 1) / 2, TB), TB>>>(ei, E, N);

    // ---- layer 1 ----
    k_gemm1t<<<g1, TB>>>(x, W1, (__half*)pA, N);
    k_gatherh<16, true, true, true><<<gw, TB>>>(A4, B4, b1, N);

    // ---- layer 2 (fused gather+GEMM) ----
    k_g2g<<<gw, TB>>>(B4, W2, b2, (__half*)pA, N);

    // ---- layer 3 ----
    k_gemmh<64, 32><<<gn, TB>>>(A4, W3, B2, N);
    k_gatherh<32, false, true, false><<<gw, TB>>>(B4, A4, b3, N);

    // ---- pool + head (fused) ----
    k_poolhead<<<GNUM, 256>>>((const __half*)pA, batch, Wa, ba, Wo, bo, out, N);
}

// round 14
// speedup vs baseline: 1.5925x; 1.5925x over previous
#include <cuda_runtime.h>
#include <cuda_fp16.h>
#include <math.h>

#define NMAX 100000
#define EMAX 3200000
#define GNUM 64
#define FIN  128
#define SCB  1024
#define NBLK ((NMAX + SCB - 1) / SCB)

// -------- device scratch --------
__device__ uint4  g_A[(size_t)NMAX * 8];     // N x (<=64) halfs, ping
__device__ uint4  g_B[(size_t)NMAX * 8];     // pong
__device__ float  g_dinv[NMAX];
__device__ int    g_deg [NMAX];
__device__ int    g_rowptr[NMAX + 1];        // block-local exclusive; [n]=total
__device__ int    g_bsum[NBLK];
__device__ int    g_boff[NBLK];
__device__ int    g_done;
__device__ int    g_rank[EMAX];
__device__ int    g_csrc[EMAX];

__device__ __forceinline__ int rp(int i, int n) {
    return (i < n) ? (g_rowptr[i] + g_boff[i / SCB]) : g_rowptr[n];
}

// -------- half helpers --------
__device__ __forceinline__ float2 uph(unsigned v) {
    __half2 h = *reinterpret_cast<__half2*>(&v);
    return __half22float2(h);
}
__device__ __forceinline__ unsigned pack2(float x, float y) {
    __half2 h = __floats2half2_rn(x, y);
    return *reinterpret_cast<unsigned*>(&h);
}
__device__ __forceinline__ uint2 pack4(float4 a) {
    return make_uint2(pack2(a.x, a.y), pack2(a.z, a.w));
}
__device__ __forceinline__ void acc8(float* a, uint4 u) {
    float2 f0 = uph(u.x), f1 = uph(u.y), f2 = uph(u.z), f3 = uph(u.w);
    a[0] += f0.x; a[1] += f0.y; a[2] += f1.x; a[3] += f1.y;
    a[4] += f2.x; a[5] += f2.y; a[6] += f3.x; a[7] += f3.y;
}

// -------- degree count on dst + per-edge rank --------
__global__ void k_prep(const int* __restrict__ ei, int E, int n) {
    int base = 2 * (blockIdx.x * blockDim.x + threadIdx.x);
    if (base >= E) return;
    if (base + 1 < E) {
        int2 d2 = *(const int2*)(ei + E + base);
        int d0 = ((unsigned)d2.x < (unsigned)n) ? d2.x : 0;
        int d1 = ((unsigned)d2.y < (unsigned)n) ? d2.y : 0;
        int r0 = atomicAdd(&g_deg[d0], 1);
        int r1 = atomicAdd(&g_deg[d1], 1);
        *(int2*)(g_rank + base) = make_int2(r0, r1);
    } else {
        int d = ei[E + base];
        if ((unsigned)d >= (unsigned)n) d = 0;
        g_rank[base] = atomicAdd(&g_deg[d], 1);
    }
}

// -------- scan phase 1 (+dinv), fused phase 2 in last block --------
__global__ void k_scan1(int n, int nb) {
    __shared__ int wsum[32];
    __shared__ bool lastblk;
    int t = threadIdx.x, lane = t & 31, w = t >> 5;
    int i = blockIdx.x * SCB + t;
    int v = (i < n) ? g_deg[i] : 0;
    if (i < n) g_dinv[i] = rsqrtf((float)v + 1.0f);
    int inc = v;
    #pragma unroll
    for (int o = 1; o < 32; o <<= 1) {
        int u = __shfl_up_sync(0xffffffffu, inc, o);
        if (lane >= o) inc += u;
    }
    if (lane == 31) wsum[w] = inc;
    __syncthreads();
    if (w == 0) {
        int s = wsum[lane];
        int sinc = s;
        #pragma unroll
        for (int o = 1; o < 32; o <<= 1) {
            int u = __shfl_up_sync(0xffffffffu, sinc, o);
            if (lane >= o) sinc += u;
        }
        wsum[lane] = sinc - s;
        if (lane == 31) g_bsum[blockIdx.x] = sinc;
    }
    __syncthreads();
    if (i < n) g_rowptr[i] = wsum[w] + inc - v;

    __threadfence();
    if (t == 0) lastblk = (atomicAdd(&g_done, 1) == nb - 1);
    __syncthreads();
    if (!lastblk) return;
    int v2 = (t < nb) ? g_bsum[t] : 0;
    int inc2 = v2;
    #pragma unroll
    for (int o = 1; o < 32; o <<= 1) {
        int u = __shfl_up_sync(0xffffffffu, inc2, o);
        if (lane >= o) inc2 += u;
    }
    __syncthreads();
    if (lane == 31) wsum[w] = inc2;
    __syncthreads();
    if (w == 0) {
        int s = wsum[lane];
        int sinc = s;
        #pragma unroll
        for (int o = 1; o < 32; o <<= 1) {
            int u = __shfl_up_sync(0xffffffffu, sinc, o);
            if (lane >= o) sinc += u;
        }
        wsum[lane] = sinc - s;
        if (lane == 31) g_rowptr[n] = sinc;
    }
    __syncthreads();
    if (t < nb) g_boff[t] = wsum[w] + inc2 - v2;
    if (t == 0) g_done = 0;
}

// -------- CSR fill: no atomics --------
__global__ void k_fill(const int* __restrict__ ei, int E, int n) {
    int base = 2 * (blockIdx.x * blockDim.x + threadIdx.x);
    if (base >= E) return;
    if (base + 1 < E) {
        int2 s2 = *(const int2*)(ei + base);
        int2 d2 = *(const int2*)(ei + E + base);
        int2 r2 = *(const int2*)(g_rank + base);
        int s0 = ((unsigned)s2.x < (unsigned)n) ? s2.x : 0;
        int s1 = ((unsigned)s2.y < (unsigned)n) ? s2.y : 0;
        int d0 = ((unsigned)d2.x < (unsigned)n) ? d2.x : 0;
        int d1 = ((unsigned)d2.y < (unsigned)n) ? d2.y : 0;
        g_csrc[rp(d0, n) + r2.x] = s0;
        g_csrc[rp(d1, n) + r2.y] = s1;
    } else {
        int s = ei[base], d = ei[E + base];
        if ((unsigned)s >= (unsigned)n || (unsigned)d >= (unsigned)n) { s = 0; d = 0; }
        g_csrc[rp(d, n) + g_rank[base]] = s;
    }
}

// -------- GEMM fp32 in (layer 1: 128->16), half out, *dinv; MLP-8 prefetch ----
__global__ void k_gemmf(const float* __restrict__ X, const float* __restrict__ W,
                        uint2* __restrict__ OUT, int n) {
    constexpr int K = 128, MOUT = 16, M4 = MOUT / 4;
    __shared__ float4 Ws[K * M4];
    int tid = threadIdx.x;
    for (int i = tid; i < K * M4; i += blockDim.x)
        Ws[i] = ((const float4*)W)[i];
    __syncthreads();
    int node = blockIdx.x * blockDim.x + tid;
    if (node >= n) return;
    const float4* xr = (const float4*)(X + (size_t)node * K);
    float4 acc[M4];
    #pragma unroll
    for (int m = 0; m < M4; m++) acc[m] = make_float4(0.f, 0.f, 0.f, 0.f);
    #pragma unroll
    for (int c = 0; c < 4; c++) {
        // prefetch 8 independent float4 loads (MLP 8)
        float4 xv[8];
        #pragma unroll
        for (int i = 0; i < 8; i++) xv[i] = __ldg(&xr[c * 8 + i]);
        #pragma unroll
        for (int i = 0; i < 8; i++) {
            int k4 = c * 8 + i;
            float4 x4 = xv[i];
            #pragma unroll
            for (int m = 0; m < M4; m++) {
                float4 w0 = Ws[(4 * k4 + 0) * M4 + m];
                float4 w1 = Ws[(4 * k4 + 1) * M4 + m];
                float4 w2 = Ws[(4 * k4 + 2) * M4 + m];
                float4 w3 = Ws[(4 * k4 + 3) * M4 + m];
                acc[m].x += x4.x * w0.x + x4.y * w1.x + x4.z * w2.x + x4.w * w3.x;
                acc[m].y += x4.x * w0.y + x4.y * w1.y + x4.z * w2.y + x4.w * w3.y;
                acc[m].z += x4.x * w0.z + x4.y * w1.z + x4.z * w2.z + x4.w * w3.z;
                acc[m].w += x4.x * w0.w + x4.y * w1.w + x4.z * w2.w + x4.w * w3.w;
            }
        }
    }
    float sc = g_dinv[node];
    uint2* orow = OUT + (size_t)node * M4;
    #pragma unroll
    for (int m = 0; m < M4; m++) {
        float4 a = acc[m];
        a.x *= sc; a.y *= sc; a.z *= sc; a.w *= sc;
        orow[m] = pack4(a);
    }
}

// -------- GEMM half in (layer 3: 64->32), half out, *dinv; prefetch x4 -------
__global__ void k_gemmh(const uint4* __restrict__ X, const float* __restrict__ W,
                        uint2* __restrict__ OUT, int n) {
    constexpr int K = 64, MOUT = 32, M4 = MOUT / 4;
    __shared__ float4 Ws[K * M4];
    int tid = threadIdx.x;
    for (int i = tid; i < K * M4; i += blockDim.x)
        Ws[i] = ((const float4*)W)[i];
    __syncthreads();
    int node = blockIdx.x * blockDim.x + tid;
    if (node >= n) return;
    const uint4* xr = X + (size_t)node * 8;
    float4 acc[M4];
    #pragma unroll
    for (int m = 0; m < M4; m++) acc[m] = make_float4(0.f, 0.f, 0.f, 0.f);
    #pragma unroll
    for (int h = 0; h < 2; h++) {
        uint4 uv[4];
        #pragma unroll
        for (int i = 0; i < 4; i++) uv[i] = __ldg(&xr[h * 4 + i]);
        #pragma unroll
        for (int i = 0; i < 4; i++) {
            int c = h * 4 + i;
            float xk[8];
            float2 f0 = uph(uv[i].x), f1 = uph(uv[i].y), f2 = uph(uv[i].z), f3 = uph(uv[i].w);
            xk[0] = f0.x; xk[1] = f0.y; xk[2] = f1.x; xk[3] = f1.y;
            xk[4] = f2.x; xk[5] = f2.y; xk[6] = f3.x; xk[7] = f3.y;
            #pragma unroll
            for (int kk = 0; kk < 8; kk++) {
                float xv = xk[kk];
                #pragma unroll
                for (int m = 0; m < M4; m++) {
                    float4 w = Ws[(8 * c + kk) * M4 + m];
                    acc[m].x += xv * w.x; acc[m].y += xv * w.y;
                    acc[m].z += xv * w.z; acc[m].w += xv * w.w;
                }
            }
        }
    }
    float sc = g_dinv[node];
    uint2* orow = OUT + (size_t)node * M4;
    #pragma unroll
    for (int m = 0; m < M4; m++) {
        float4 a = acc[m];
        a.x *= sc; a.y *= sc; a.z *= sc; a.w *= sc;
        orow[m] = pack4(a);
    }
}

// -------- warp-per-node half gather --------
template<int F, bool RELU, bool HASB, bool SCALEOUT>
__global__ void k_gatherh(const uint4* __restrict__ src, uint4* __restrict__ dst,
                          const float* __restrict__ bias, int n) {
    constexpr int LPR = F / 8;
    constexpr int EPW = 32 / LPR;
    int wid = (blockIdx.x * blockDim.x + threadIdx.x) >> 5;
    if (wid >= n) return;
    int lane = threadIdx.x & 31;
    int e_l = lane / LPR;
    int g   = lane % LPR;
    int beg = rp(wid, n), end = rp(wid + 1, n);
    float a0[8] = {0,0,0,0,0,0,0,0};
    float a1[8] = {0,0,0,0,0,0,0,0};
    int j = beg + e_l;
    for (; j + EPW < end; j += 2 * EPW) {
        int s0 = __ldg(&g_csrc[j]);
        int s1 = __ldg(&g_csrc[j + EPW]);
        uint4 u0 = __ldg(&src[(size_t)s0 * LPR + g]);
        uint4 u1 = __ldg(&src[(size_t)s1 * LPR + g]);
        acc8(a0, u0);
        acc8(a1, u1);
    }
    if (j < end) {
        int s0 = __ldg(&g_csrc[j]);
        uint4 u0 = __ldg(&src[(size_t)s0 * LPR + g]);
        acc8(a0, u0);
    }
    #pragma unroll
    for (int q = 0; q < 8; q++) a0[q] += a1[q];
    #pragma unroll
    for (int off = 16; off >= LPR; off >>= 1) {
        #pragma unroll
        for (int q = 0; q < 8; q++)
            a0[q] += __shfl_xor_sync(0xffffffffu, a0[q], off);
    }
    if (lane < LPR) {
        uint4 hv = src[(size_t)wid * LPR + g];
        acc8(a0, hv);
        float di = g_dinv[wid];
        #pragma unroll
        for (int q = 0; q < 8; q++) a0[q] *= di;
        if (HASB) {
            #pragma unroll
            for (int q = 0; q < 8; q++) a0[q] += __ldg(&bias[8 * g + q]);
        }
        if (RELU) {
            #pragma unroll
            for (int q = 0; q < 8; q++) a0[q] = fmaxf(a0[q], 0.f);
        }
        if (SCALEOUT) {
            #pragma unroll
            for (int q = 0; q < 8; q++) a0[q] *= di;
        }
        uint4 o;
        o.x = pack2(a0[0], a0[1]); o.y = pack2(a0[2], a0[3]);
        o.z = pack2(a0[4], a0[5]); o.w = pack2(a0[6], a0[7]);
        dst[(size_t)wid * LPR + g] = o;
    }
}

// -------- FUSED layer 2: gather(16) + GEMM 16->64 + bias + relu --------
__global__ void k_g2g(const uint4* __restrict__ src, const float* __restrict__ W2,
                      const float* __restrict__ b2, __half* __restrict__ OUT, int n) {
    __shared__ float Ws[16 * 64];
    int tid = threadIdx.x;
    for (int i = tid; i < 16 * 64; i += blockDim.x) Ws[i] = W2[i];
    __syncthreads();
    int wid = (blockIdx.x * blockDim.x + tid) >> 5;
    if (wid >= n) return;
    int lane = tid & 31;
    int e_l = lane >> 1;
    int g   = lane & 1;
    int beg = rp(wid, n), end = rp(wid + 1, n);
    float a0[8] = {0,0,0,0,0,0,0,0};
    float a1[8] = {0,0,0,0,0,0,0,0};
    int j = beg + e_l;
    for (; j + 16 < end; j += 32) {
        int s0 = __ldg(&g_csrc[j]);
        int s1 = __ldg(&g_csrc[j + 16]);
        uint4 u0 = __ldg(&src[(size_t)s0 * 2 + g]);
        uint4 u1 = __ldg(&src[(size_t)s1 * 2 + g]);
        acc8(a0, u0);
        acc8(a1, u1);
    }
    if (j < end) {
        int s0 = __ldg(&g_csrc[j]);
        uint4 u0 = __ldg(&src[(size_t)s0 * 2 + g]);
        acc8(a0, u0);
    }
    #pragma unroll
    for (int q = 0; q < 8; q++) a0[q] += a1[q];
    #pragma unroll
    for (int off = 16; off >= 2; off >>= 1) {
        #pragma unroll
        for (int q = 0; q < 8; q++)
            a0[q] += __shfl_xor_sync(0xffffffffu, a0[q], off);
    }
    uint4 hv = __ldg(&src[(size_t)wid * 2 + g]);
    acc8(a0, hv);
    float di = g_dinv[wid];
    #pragma unroll
    for (int q = 0; q < 8; q++) a0[q] *= di;
    float agg[16];
    #pragma unroll
    for (int q = 0; q < 8; q++) {
        agg[q]     = __shfl_sync(0xffffffffu, a0[q], 0);
        agg[8 + q] = __shfl_sync(0xffffffffu, a0[q], 1);
    }
    float acc1 = __ldg(&b2[lane]);
    float acc2 = __ldg(&b2[lane + 32]);
    #pragma unroll
    for (int k = 0; k < 16; k++) {
        acc1 += agg[k] * Ws[k * 64 + lane];
        acc2 += agg[k] * Ws[k * 64 + lane + 32];
    }
    __half* orow = OUT + (size_t)wid * 64;
    orow[lane]      = __float2half(fmaxf(acc1, 0.f));
    orow[lane + 32] = __float2half(fmaxf(acc2, 0.f));
}

// -------- FUSED mean pool + MLP head --------
__global__ void k_poolhead(const __half* __restrict__ fsrc, const int* __restrict__ batch,
                           const float* __restrict__ Wa, const float* __restrict__ ba,
                           const float* __restrict__ Wo, const float* __restrict__ bo,
                           float* __restrict__ out, int n) {
    __shared__ int bounds[2];
    __shared__ float sh[256];
    __shared__ float ps[32];
    __shared__ float a[64];
    int g = blockIdx.x;
    int t = threadIdx.x;
    if (t == 0) {
        int lo = 0, hi = n;
        while (lo < hi) { int mid = (lo + hi) >> 1; if (batch[mid] < g) lo = mid + 1; else hi = mid; }
        bounds[0] = lo;
        int lo2 = lo; hi = n;
        while (lo2 < hi) { int mid = (lo2 + hi) >> 1; if (batch[mid] < g + 1) lo2 = mid + 1; else hi = mid; }
        bounds[1] = lo2;
    }
    __syncthreads();
    int beg = bounds[0], cnt = bounds[1] - bounds[0];
    int f = t & 31, p = t >> 5;
    float s = 0.f;
    for (int k = p; k < cnt; k += 8)
        s += __half2float(fsrc[(size_t)(beg + k) * 32 + f]);
    sh[t] = s;
    __syncthreads();
    if (p == 0) {
        float tot = 0.f;
        #pragma unroll
        for (int q = 0; q < 8; q++) tot += sh[q * 32 + f];
        ps[f] = tot / fmaxf((float)cnt, 1.f);
    }
    __syncthreads();
    if (t < 64) {
        float acc = ba[t];
        #pragma unroll
        for (int k = 0; k < 32; k++) acc += ps[k] * Wa[k * 64 + t];
        a[t] = fmaxf(acc, 0.f);
    }
    __syncthreads();
    if (t < 32) {
        float o = bo[t];
        #pragma unroll
        for (int k = 0; k < 64; k++) o += a[k] * Wo[k * 32 + t];
        out[g * 32 + t] = tanhf(o);
    }
}

// ============================================================================
extern "C" void kernel_launch(void* const* d_in, const int* in_sizes, int n_in,
                              void* d_out, int out_size) {
    const float* x     = (const float*)d_in[0];
    const int*   ei    = (const int*)d_in[1];
    const int*   batch = (const int*)d_in[2];
    const float* W1 = (const float*)d_in[3];  const float* b1 = (const float*)d_in[4];
    const float* W2 = (const float*)d_in[5];  const float* b2 = (const float*)d_in[6];
    const float* W3 = (const float*)d_in[7];  const float* b3 = (const float*)d_in[8];
    const float* Wa = (const float*)d_in[9];  const float* ba = (const float*)d_in[10];
    const float* Wo = (const float*)d_in[11]; const float* bo = (const float*)d_in[12];
    float* out = (float*)d_out;

    int N = in_sizes[0] / FIN;
    int E = in_sizes[1] / 2;
    if (N > NMAX) N = NMAX;
    if (E > EMAX) E = EMAX;
    int nb = (N + SCB - 1) / SCB;

    void *pA = nullptr, *pB = nullptr, *pDeg = nullptr;
    cudaGetSymbolAddress(&pA, g_A);
    cudaGetSymbolAddress(&pB, g_B);
    cudaGetSymbolAddress(&pDeg, g_deg);
    uint4* A4 = (uint4*)pA;  uint2* A2 = (uint2*)pA;
    uint4* B4 = (uint4*)pB;  uint2* B2 = (uint2*)pB;

    const int TB = 256;
    auto blocks = [](long long work, int tb) { return (int)((work + tb - 1) / tb); };
    int gw = blocks((long long)N * 32, TB);
    int gn = blocks(N, TB);

    // ---- CSR build + dinv ----
    cudaMemsetAsync(pDeg, 0, (size_t)N * sizeof(int));
    k_prep<<<blocks((E + 1) / 2, TB), TB>>>(ei, E, N);
    k_scan1<<<nb, SCB>>>(N, nb);
    k_fill<<<blocks((E + 1) / 2, TB), TB>>>(ei, E, N);

    // ---- layer 1 ----
    k_gemmf<<<gn, TB>>>(x, W1, A2, N);
    k_gatherh<16, true, true, true><<<gw, TB>>>(A4, B4, b1, N);

    // ---- layer 2 (fused gather+GEMM) ----
    k_g2g<<<gw, TB>>>(B4, W2, b2, (__half*)pA, N);

    // ---- layer 3 ----
    k_gemmh<<<gn, TB>>>(A4, W3, B2, N);
    k_gatherh<32, false, true, false><<<gw, TB>>>(B4, A4, b3, N);

    // ---- pool + head (fused) ----
    k_poolhead<<<GNUM, 256>>>((const __half*)pA, batch, Wa, ba, Wo, bo, out, N);
}